// round 13
// baseline (speedup 1.0000x reference)
#include <cuda_runtime.h>
#include <cuda_bf16.h>
#include <cstdint>
#include <cstddef>

#define H 2048
#define NACT 64
#define STEPS 32
#define NLAYERS 2

// ---------------- device state ----------------
__device__ __align__(16) float g_h[2][NLAYERS][H];   // [parity][layer]
__device__ __align__(16) float g_c[NLAYERS][H];
__device__ __align__(16) float g_x[H];
__device__ __align__(16) float g_part[2][NACT];      // head partial dots
__device__ __align__(16) float g_gacc[512][4][16];   // cell partial gates
__device__ int   g_gcnt[512];                        // cell tile election
__device__ float g_logp_sum;
__device__ int   g_action;
__device__ int   g_done;

// bf16 weights, HMMA-fragment-ready (validated R9/R11/R12):
// unit u (16B): lane=u&31, c=(u>>5)&255, T=(u>>13)&511, l=u>>22.
// Tile T covers rows' 16T..16T+15, row' = j*4+gate; chunk c covers concat-k
// 16c..16c+15 (k<2048: W_ih, else W_hh). The 16B is the exact m16n8k16
// A-fragment for LDG.128 at lane*16.
__device__ __align__(16) unsigned char g_wbf[(size_t)NLAYERS * 2 * 4 * H * H * 2];

// ---------------- threefry2x32-20 (bit-exact JAX core) ----------------
__device__ __forceinline__ uint32_t rotl32(uint32_t v, int d) {
    return (v << d) | (v >> (32 - d));
}
__device__ __forceinline__ void threefry2x32(uint32_t k0, uint32_t k1,
                                             uint32_t x0, uint32_t x1,
                                             uint32_t& o0, uint32_t& o1) {
    const uint32_t ks2 = k0 ^ k1 ^ 0x1BD11BDAu;
    x0 += k0; x1 += k1;
    x0 += x1; x1 = rotl32(x1, 13); x1 ^= x0;
    x0 += x1; x1 = rotl32(x1, 15); x1 ^= x0;
    x0 += x1; x1 = rotl32(x1, 26); x1 ^= x0;
    x0 += x1; x1 = rotl32(x1, 6);  x1 ^= x0;
    x0 += k1; x1 += ks2 + 1u;
    x0 += x1; x1 = rotl32(x1, 17); x1 ^= x0;
    x0 += x1; x1 = rotl32(x1, 29); x1 ^= x0;
    x0 += x1; x1 = rotl32(x1, 16); x1 ^= x0;
    x0 += x1; x1 = rotl32(x1, 24); x1 ^= x0;
    x0 += ks2; x1 += k0 + 2u;
    x0 += x1; x1 = rotl32(x1, 13); x1 ^= x0;
    x0 += x1; x1 = rotl32(x1, 15); x1 ^= x0;
    x0 += x1; x1 = rotl32(x1, 26); x1 ^= x0;
    x0 += x1; x1 = rotl32(x1, 6);  x1 ^= x0;
    x0 += k0; x1 += k1 + 3u;
    x0 += x1; x1 = rotl32(x1, 17); x1 ^= x0;
    x0 += x1; x1 = rotl32(x1, 29); x1 ^= x0;
    x0 += x1; x1 = rotl32(x1, 16); x1 ^= x0;
    x0 += x1; x1 = rotl32(x1, 24); x1 ^= x0;
    x0 += k1; x1 += ks2 + 4u;
    x0 += x1; x1 = rotl32(x1, 13); x1 ^= x0;
    x0 += x1; x1 = rotl32(x1, 15); x1 ^= x0;
    x0 += x1; x1 = rotl32(x1, 26); x1 ^= x0;
    x0 += x1; x1 = rotl32(x1, 6);  x1 ^= x0;
    x0 += ks2; x1 += k0 + 5u;
    o0 = x0; o1 = x1;
}
__device__ __forceinline__ float jax_uniform(uint32_t bits) {
    const float tiny = 1.1754943508222875e-38f;
    uint32_t fb = (bits >> 9) | 0x3f800000u;
    float u = __uint_as_float(fb) - 1.0f;
    u = u * 1.0f + tiny;
    return fmaxf(tiny, u);
}
__device__ __forceinline__ uint32_t bf2_bits(float a, float b) {
    __nv_bfloat162 v = __floats2bfloat162_rn(a, b);
    return *reinterpret_cast<uint32_t*>(&v);
}

// ---------------- weight convert: fp32 -> HMMA-fragment bf16 tiles ----------------
__global__ void convert_kernel(const float* __restrict__ w_ih,
                               const float* __restrict__ w_hh) {
    const size_t NU = (size_t)NLAYERS * 512 * 256 * 32;   // 16B units
    size_t stride = (size_t)gridDim.x * blockDim.x;
    for (size_t u = (size_t)blockIdx.x * blockDim.x + threadIdx.x; u < NU; u += stride) {
        int lane = (int)(u & 31);
        int c    = (int)((u >> 5) & 255);
        int T    = (int)((u >> 13) & 511);
        int l    = (int)(u >> 22);
        int gid  = lane >> 2, t4 = lane & 3;
        int k0c  = 16 * c + 2 * t4;            // concat-k
        int which = k0c >> 11;                  // 0: W_ih, 1: W_hh
        int kk   = k0c & 2047;
        const float* W = (which ? w_hh : w_ih) + (size_t)l * 4 * H * H;
        int rl0 = gid, rl1 = gid + 8;
        int j0 = 4 * T + (rl0 >> 2), g0 = rl0 & 3;
        int j1 = 4 * T + (rl1 >> 2), g1 = rl1 & 3;
        const float* r0p = W + ((size_t)g0 * H + j0) * H;
        const float* r1p = W + ((size_t)g1 * H + j1) * H;
        uint4 o;
        o.x = bf2_bits(r0p[kk],     r0p[kk + 1]);
        o.y = bf2_bits(r1p[kk],     r1p[kk + 1]);
        o.z = bf2_bits(r0p[kk + 8], r0p[kk + 9]);
        o.w = bf2_bits(r1p[kk + 8], r1p[kk + 9]);
        reinterpret_cast<uint4*>(g_wbf)[u] = o;
    }
}

// ---------------- init ----------------
__global__ void init_kernel(const float* __restrict__ start_token) {
    int i = blockIdx.x * blockDim.x + threadIdx.x;
    if (i < H) {
        g_x[i] = start_token[i];
        g_c[0][i] = 0.f; g_c[1][i] = 0.f;
        g_h[0][0][i] = 0.f; g_h[0][1][i] = 0.f;
        g_h[1][0][i] = 0.f; g_h[1][1][i] = 0.f;
        if (i < 512) g_gcnt[i] = 0;
        if (i == 0) { g_logp_sum = 0.f; g_action = 0; g_done = 0; }
    }
}

// ---------------- HMMA LSTM cell, K-split across 4 blocks ----------------
// grid = 2048 blocks x 256 threads (8 warps). Block (tile = bid>>2, kb = bid&3)
// covers tile T (16 rows' = 4 j x 4 gates) over concat K-range [kb*1024, +1024).
// Warp w: 8 chunks (4 KB stream), groups of 4 double-buffered. 16 partials ->
// g_gacc[tile][kb]; last-of-4 block fuses gates (fixed-order sum, deterministic).
__global__ void __launch_bounds__(256)
cell_kernel(const float* __restrict__ bih, const float* __restrict__ bhh,
            int layer, int t) {
    __shared__ uint32_t sv[512];         // this block's K-slice as bf16x2 pairs
    __shared__ float spart[8][16];
    __shared__ int s_last;
    const int tid  = threadIdx.x;
    const int wid  = tid >> 5;
    const int lane = tid & 31;
    const int tile = blockIdx.x >> 2;
    const int kb   = blockIdx.x & 3;
    const int par_in  = t & 1;
    const int par_out = (t + 1) & 1;

    // stage this block's 1024-element vector slice
    {
        const float2* vx = reinterpret_cast<const float2*>(
            (layer == 0) ? g_x : g_h[par_out][0]);
        const float2* vh = reinterpret_cast<const float2*>(g_h[par_in][layer]);
#pragma unroll
        for (int q = tid; q < 512; q += 256) {
            int qg = kb * 512 + q;               // global float2 index (0..2047)
            float2 f = (qg < 1024) ? vx[qg] : vh[qg - 1024];
            sv[q] = bf2_bits(f.x, f.y);
        }
    }
    __syncthreads();

    const uint4* wb = reinterpret_cast<const uint4*>(g_wbf)
                    + ((size_t)(layer * 512 + tile) * 256 + kb * 64 + 8 * wid) * 32;
    const int t4 = lane & 3, gid = lane >> 2;

    float c0 = 0.f, c1 = 0.f, c2 = 0.f, c3 = 0.f;
    uint4 a[2][4];
#pragma unroll
    for (int i = 0; i < 4; i++) a[0][i] = wb[i * 32 + lane];

#pragma unroll
    for (int g = 0; g < 2; g++) {
        const int cur = g & 1;
        if (g < 1) {
            const uint4* nb = wb + 4 * 32;
#pragma unroll
            for (int i = 0; i < 4; i++) a[cur ^ 1][i] = nb[i * 32 + lane];
        }
#pragma unroll
        for (int i = 0; i < 4; i++) {
            const int lc = 8 * wid + g * 4 + i;   // local chunk 0..63
            uint32_t b0 = sv[8 * lc + t4];
            uint32_t b1 = sv[8 * lc + 4 + t4];
            asm volatile(
                "mma.sync.aligned.m16n8k16.row.col.f32.bf16.bf16.f32 "
                "{%0,%1,%2,%3}, {%4,%5,%6,%7}, {%8,%9}, {%0,%1,%2,%3};"
                : "+f"(c0), "+f"(c1), "+f"(c2), "+f"(c3)
                : "r"(a[cur][i].x), "r"(a[cur][i].y),
                  "r"(a[cur][i].z), "r"(a[cur][i].w),
                  "r"(b0), "r"(b1));
        }
    }

    // C columns all equal: c0 = row' gid partial, c2 = row' gid+8 partial.
    if (t4 == 0) {
        spart[wid][gid]     = c0;
        spart[wid][gid + 8] = c2;
    }
    __syncthreads();

    if (tid < 16) {
        float s = 0.f;
#pragma unroll
        for (int k = 0; k < 8; k++) s += spart[k][tid];
        g_gacc[tile][kb][tid] = s;
    }
    if (tid == 0) {
        __threadfence();
        int old = atomicAdd(&g_gcnt[tile], 1);
        s_last = (old == 3) ? 1 : 0;
        if (s_last) g_gcnt[tile] = 0;
    }
    __syncthreads();
    if (!s_last) return;
    __threadfence();                        // acquire all 4 blocks' partials

    if (tid < 4) {
        const int j = 4 * tile + tid;
        float gate[4];
#pragma unroll
        for (int gt = 0; gt < 4; gt++) {
            const int rl = tid * 4 + gt;
            gate[gt] = ((g_gacc[tile][0][rl] + g_gacc[tile][1][rl])
                      + (g_gacc[tile][2][rl] + g_gacc[tile][3][rl]));
        }
        float gi = gate[0] + bih[j]         + bhh[j];
        float gf = gate[1] + bih[H + j]     + bhh[H + j];
        float gg = gate[2] + bih[2 * H + j] + bhh[2 * H + j];
        float go = gate[3] + bih[3 * H + j] + bhh[3 * H + j];
        float i_ = 1.0f / (1.0f + expf(-gi));
        float f_ = 1.0f / (1.0f + expf(-gf));
        float g_ = tanhf(gg);
        float o_ = 1.0f / (1.0f + expf(-go));
        float cn = f_ * g_c[layer][j] + i_ * g_;
        g_c[layer][j] = cn;
        g_h[par_out][layer][j] = o_ * tanhf(cn);
    }
}

// ---------------- fused head + sample ----------------
__global__ void __launch_bounds__(256)
head_sample_kernel(const float* __restrict__ hw, const float* __restrict__ hb,
                   const float* __restrict__ action_emb,
                   int t, float* __restrict__ out, int out_size) {
    const int r    = blockIdx.x & (NACT - 1);
    const int half = blockIdx.x >> 6;
    const int tid  = threadIdx.x;
    const int par_out = (t + 1) & 1;

    {
        const float4* row = reinterpret_cast<const float4*>(hw + (size_t)r * H);
        const float4* v4  = reinterpret_cast<const float4*>(g_h[par_out][1]);
        int k = half * 256 + tid;
        float4 a = row[k];
        float4 b = v4[k];
        float s = a.x * b.x + a.y * b.y + a.z * b.z + a.w * b.w;
#pragma unroll
        for (int o = 16; o; o >>= 1) s += __shfl_xor_sync(0xffffffffu, s, o);
        __shared__ float sm[8];
        if ((tid & 31) == 0) sm[tid >> 5] = s;
        __syncthreads();
        if (tid == 0) {
            g_part[half][r] = sm[0] + sm[1] + sm[2] + sm[3]
                            + sm[4] + sm[5] + sm[6] + sm[7];
        }
    }

    __shared__ int s_last;
    if (tid == 0) {
        __threadfence();
        int old = atomicAdd(&g_done, 1);
        s_last = (old == 2 * NACT - 1) ? 1 : 0;
        if (s_last) g_done = 0;
    }
    __syncthreads();
    if (!s_last) return;
    __threadfence();

    __shared__ float sl[NACT];
    if (tid < 32) {
        const int lane = tid;
        float l0 = g_part[0][lane]      + g_part[1][lane]      + hb[lane];
        float l1 = g_part[0][lane + 32] + g_part[1][lane + 32] + hb[lane + 32];
        sl[lane] = l0;
        sl[lane + 32] = l1;

        uint32_t kk0, kk1;
        threefry2x32(0u, 42u, 0u, (uint32_t)t, kk0, kk1);
        uint32_t a0, a1, b0, b1;
        threefry2x32(kk0, kk1, 0u, (uint32_t)lane,        a0, a1);
        threefry2x32(kk0, kk1, 0u, (uint32_t)(lane + 32), b0, b1);
        float u0 = jax_uniform(a0 ^ a1);
        float u1 = jax_uniform(b0 ^ b1);
        float gum0 = -logf(-logf(u0));
        float gum1 = -logf(-logf(u1));

        float v0 = l0 + gum0;
        float v1 = l1 + gum1;

        float bestv; int besti;
        if (v1 > v0) { bestv = v1; besti = lane + 32; }
        else         { bestv = v0; besti = lane; }
#pragma unroll
        for (int o = 16; o; o >>= 1) {
            float ov = __shfl_xor_sync(0xffffffffu, bestv, o);
            int   oi = __shfl_xor_sync(0xffffffffu, besti, o);
            if (ov > bestv || (ov == bestv && oi < besti)) { bestv = ov; besti = oi; }
        }
        float mx = fmaxf(l0, l1);
#pragma unroll
        for (int o = 16; o; o >>= 1) mx = fmaxf(mx, __shfl_xor_sync(0xffffffffu, mx, o));
        float se = expf(l0 - mx) + expf(l1 - mx);
#pragma unroll
        for (int o = 16; o; o >>= 1) se += __shfl_xor_sync(0xffffffffu, se, o);

        if (lane == 0) {
            float logp = (sl[besti] - mx) - logf(se);
            float news = g_logp_sum + logp;
            g_logp_sum = news;
            g_action   = besti;
            out[t] = (float)besti;
            if (t == STEPS - 1 && out_size > STEPS) out[STEPS] = news;
        }
    }
    __syncthreads();
    int a = g_action;
    const float* src = action_emb + (size_t)a * H;
    for (int k = tid; k < H; k += 256) g_x[k] = src[k];
}

// ---------------- launch ----------------
extern "C" void kernel_launch(void* const* d_in, const int* in_sizes, int n_in,
                              void* d_out, int out_size) {
    const float* start_token = (const float*)d_in[0];
    const float* action_emb  = (const float*)d_in[1];
    const float* w_ih        = (const float*)d_in[2];
    const float* w_hh        = (const float*)d_in[3];
    const float* b_ih        = (const float*)d_in[4];
    const float* b_hh        = (const float*)d_in[5];
    const float* head_w      = (const float*)d_in[6];
    const float* head_b      = (const float*)d_in[7];
    float* out = (float*)d_out;

    convert_kernel<<<4096, 256>>>(w_ih, w_hh);
    init_kernel<<<(H + 255) / 256, 256>>>(start_token);

    for (int t = 0; t < STEPS; t++) {
        for (int l = 0; l < NLAYERS; l++) {
            cell_kernel<<<2048, 256>>>(b_ih + (size_t)l * 4 * H,
                                       b_hh + (size_t)l * 4 * H,
                                       l, t);
        }
        head_sample_kernel<<<2 * NACT, 256>>>(head_w + (size_t)t * NACT * H,
                                              head_b + (size_t)t * NACT,
                                              action_emb, t, out, out_size);
    }
}

// round 14
// speedup vs baseline: 1.3376x; 1.3376x over previous
#include <cuda_runtime.h>
#include <cuda_bf16.h>
#include <cstdint>
#include <cstddef>

#define H 2048
#define NACT 64
#define STEPS 32
#define NLAYERS 2

// ---------------- device state ----------------
__device__ __align__(16) float g_h[2][NLAYERS][H];   // [parity][layer]
__device__ __align__(16) float g_c[NLAYERS][H];
__device__ __align__(16) float g_x[H];
__device__ __align__(16) float g_part[2][NACT];      // head partial dots
__device__ float g_logp_sum;
__device__ int   g_action;
__device__ int   g_done;

// bf16 weights, HMMA-fragment-ready (validated R9/R11/R12):
// unit u (16B): lane=u&31, c=(u>>5)&255, T=(u>>13)&511, l=u>>22.
// Tile T covers rows' 16T..16T+15, row' = j*4+gate; chunk c covers concat-k
// 16c..16c+15 (k<2048: W_ih, else W_hh). The 16B is the exact m16n8k16
// A-fragment for LDG.128/LDS.128 at lane*16. Tile = 128KB contiguous;
// stage s = bytes [s*16384, s*16384+16384) = chunks 32s..32s+31.
__device__ __align__(16) unsigned char g_wbf[(size_t)NLAYERS * 2 * 4 * H * H * 2];

// ---------------- threefry2x32-20 (bit-exact JAX core) ----------------
__device__ __forceinline__ uint32_t rotl32(uint32_t v, int d) {
    return (v << d) | (v >> (32 - d));
}
__device__ __forceinline__ void threefry2x32(uint32_t k0, uint32_t k1,
                                             uint32_t x0, uint32_t x1,
                                             uint32_t& o0, uint32_t& o1) {
    const uint32_t ks2 = k0 ^ k1 ^ 0x1BD11BDAu;
    x0 += k0; x1 += k1;
    x0 += x1; x1 = rotl32(x1, 13); x1 ^= x0;
    x0 += x1; x1 = rotl32(x1, 15); x1 ^= x0;
    x0 += x1; x1 = rotl32(x1, 26); x1 ^= x0;
    x0 += x1; x1 = rotl32(x1, 6);  x1 ^= x0;
    x0 += k1; x1 += ks2 + 1u;
    x0 += x1; x1 = rotl32(x1, 17); x1 ^= x0;
    x0 += x1; x1 = rotl32(x1, 29); x1 ^= x0;
    x0 += x1; x1 = rotl32(x1, 16); x1 ^= x0;
    x0 += x1; x1 = rotl32(x1, 24); x1 ^= x0;
    x0 += ks2; x1 += k0 + 2u;
    x0 += x1; x1 = rotl32(x1, 13); x1 ^= x0;
    x0 += x1; x1 = rotl32(x1, 15); x1 ^= x0;
    x0 += x1; x1 = rotl32(x1, 26); x1 ^= x0;
    x0 += x1; x1 = rotl32(x1, 6);  x1 ^= x0;
    x0 += k0; x1 += k1 + 3u;
    x0 += x1; x1 = rotl32(x1, 17); x1 ^= x0;
    x0 += x1; x1 = rotl32(x1, 29); x1 ^= x0;
    x0 += x1; x1 = rotl32(x1, 16); x1 ^= x0;
    x0 += x1; x1 = rotl32(x1, 24); x1 ^= x0;
    x0 += k1; x1 += ks2 + 4u;
    x0 += x1; x1 = rotl32(x1, 13); x1 ^= x0;
    x0 += x1; x1 = rotl32(x1, 15); x1 ^= x0;
    x0 += x1; x1 = rotl32(x1, 26); x1 ^= x0;
    x0 += x1; x1 = rotl32(x1, 6);  x1 ^= x0;
    x0 += ks2; x1 += k0 + 5u;
    o0 = x0; o1 = x1;
}
__device__ __forceinline__ float jax_uniform(uint32_t bits) {
    const float tiny = 1.1754943508222875e-38f;
    uint32_t fb = (bits >> 9) | 0x3f800000u;
    float u = __uint_as_float(fb) - 1.0f;
    u = u * 1.0f + tiny;
    return fmaxf(tiny, u);
}
__device__ __forceinline__ uint32_t bf2_bits(float a, float b) {
    __nv_bfloat162 v = __floats2bfloat162_rn(a, b);
    return *reinterpret_cast<uint32_t*>(&v);
}

// ---------------- weight convert: fp32 -> HMMA-fragment bf16 tiles ----------------
__global__ void convert_kernel(const float* __restrict__ w_ih,
                               const float* __restrict__ w_hh) {
    const size_t NU = (size_t)NLAYERS * 512 * 256 * 32;   // 16B units
    size_t stride = (size_t)gridDim.x * blockDim.x;
    for (size_t u = (size_t)blockIdx.x * blockDim.x + threadIdx.x; u < NU; u += stride) {
        int lane = (int)(u & 31);
        int c    = (int)((u >> 5) & 255);
        int T    = (int)((u >> 13) & 511);
        int l    = (int)(u >> 22);
        int gid  = lane >> 2, t4 = lane & 3;
        int k0c  = 16 * c + 2 * t4;            // concat-k
        int which = k0c >> 11;                  // 0: W_ih, 1: W_hh
        int kk   = k0c & 2047;
        const float* W = (which ? w_hh : w_ih) + (size_t)l * 4 * H * H;
        int rl0 = gid, rl1 = gid + 8;
        int j0 = 4 * T + (rl0 >> 2), g0 = rl0 & 3;
        int j1 = 4 * T + (rl1 >> 2), g1 = rl1 & 3;
        const float* r0p = W + ((size_t)g0 * H + j0) * H;
        const float* r1p = W + ((size_t)g1 * H + j1) * H;
        uint4 o;
        o.x = bf2_bits(r0p[kk],     r0p[kk + 1]);
        o.y = bf2_bits(r1p[kk],     r1p[kk + 1]);
        o.z = bf2_bits(r0p[kk + 8], r0p[kk + 9]);
        o.w = bf2_bits(r1p[kk + 8], r1p[kk + 9]);
        reinterpret_cast<uint4*>(g_wbf)[u] = o;
    }
}

// ---------------- init ----------------
__global__ void init_kernel(const float* __restrict__ start_token) {
    int i = blockIdx.x * blockDim.x + threadIdx.x;
    if (i < H) {
        g_x[i] = start_token[i];
        g_c[0][i] = 0.f; g_c[1][i] = 0.f;
        g_h[0][0][i] = 0.f; g_h[0][1][i] = 0.f;
        g_h[1][0][i] = 0.f; g_h[1][1][i] = 0.f;
        if (i == 0) { g_logp_sum = 0.f; g_action = 0; g_done = 0; }
    }
}

#define CP_ASYNC_16(smem_u32, gptr) \
    asm volatile("cp.async.cg.shared.global [%0], [%1], 16;" \
                 :: "r"(smem_u32), "l"(gptr) : "memory")
#define CP_COMMIT() asm volatile("cp.async.commit_group;" ::: "memory")

// ---------------- HMMA LSTM cell, cp.async double-buffered pipeline ----------------
// grid = 512 blocks x 256 threads (8 warps). Block = tile T (16 rows' = 4 j x
// 4 gates, K=4096 = 128 KB). 8 stages x 16 KB through a 2-stage smem ring via
// cp.async (register-decoupled DRAM stream). Warp w consumes chunks 4w..4w+3
// of each stage. 8 partials reduced in smem; 4 threads fuse gates.
__global__ void __launch_bounds__(256)
cell_kernel(const float* __restrict__ bih, const float* __restrict__ bhh,
            int layer, int t) {
    __shared__ __align__(16) unsigned char sa[2][16384];
    __shared__ uint32_t sv[2048];        // concat [x;h] as bf16x2 pairs
    __shared__ float spart[8][16];
    const int tid  = threadIdx.x;
    const int wid  = tid >> 5;
    const int lane = tid & 31;
    const int par_in  = t & 1;
    const int par_out = (t + 1) & 1;
    const int T = blockIdx.x;

    const unsigned char* wt = g_wbf + (size_t)(layer * 512 + T) * 131072;

    // issue stage 0 immediately (fire-and-forget)
    {
        uint32_t s0 = (uint32_t)__cvta_generic_to_shared(&sa[0][tid * 16]);
        const unsigned char* gp = wt + tid * 16;
#pragma unroll
        for (int i = 0; i < 4; i++)
            CP_ASYNC_16(s0 + i * 4096, gp + (size_t)i * 4096);
        CP_COMMIT();
    }

    // stage concat vector while stage 0 is in flight
    {
        const float2* vx = reinterpret_cast<const float2*>(
            (layer == 0) ? g_x : g_h[par_out][0]);
        const float2* vh = reinterpret_cast<const float2*>(g_h[par_in][layer]);
#pragma unroll
        for (int q = tid; q < 2048; q += 256) {
            float2 f = (q < 1024) ? vx[q] : vh[q - 1024];
            sv[q] = bf2_bits(f.x, f.y);
        }
    }

    const int t4 = lane & 3, gid = lane >> 2;
    float c0 = 0.f, c1 = 0.f, c2 = 0.f, c3 = 0.f;

    for (int s = 0; s < 8; s++) {
        if (s < 7) {
            // issue next stage into the other buffer
            uint32_t sn = (uint32_t)__cvta_generic_to_shared(
                &sa[(s + 1) & 1][tid * 16]);
            const unsigned char* gp = wt + (size_t)(s + 1) * 16384 + tid * 16;
#pragma unroll
            for (int i = 0; i < 4; i++)
                CP_ASYNC_16(sn + i * 4096, gp + (size_t)i * 4096);
            CP_COMMIT();
            asm volatile("cp.async.wait_group 1;" ::: "memory");  // stage s done
        } else {
            asm volatile("cp.async.wait_group 0;" ::: "memory");
        }
        __syncthreads();   // stage s visible to all

        const unsigned char* buf = sa[s & 1];
#pragma unroll
        for (int i = 0; i < 4; i++) {
            const int q = 4 * wid + i;              // chunk within stage
            uint4 a = *reinterpret_cast<const uint4*>(buf + q * 512 + lane * 16);
            const int c = s * 32 + q;               // global chunk
            uint32_t b0 = sv[8 * c + t4];
            uint32_t b1 = sv[8 * c + 4 + t4];
            asm volatile(
                "mma.sync.aligned.m16n8k16.row.col.f32.bf16.bf16.f32 "
                "{%0,%1,%2,%3}, {%4,%5,%6,%7}, {%8,%9}, {%0,%1,%2,%3};"
                : "+f"(c0), "+f"(c1), "+f"(c2), "+f"(c3)
                : "r"(a.x), "r"(a.y), "r"(a.z), "r"(a.w), "r"(b0), "r"(b1));
        }
        __syncthreads();   // compute done before buffer reuse next iteration
    }

    // C columns all equal: c0 = row' gid partial, c2 = row' gid+8 partial.
    if (t4 == 0) {
        spart[wid][gid]     = c0;
        spart[wid][gid + 8] = c2;
    }
    __syncthreads();

    if (tid < 4) {
        const int j = 4 * T + tid;
        float gate[4];
#pragma unroll
        for (int gt = 0; gt < 4; gt++) {
            const int rl = tid * 4 + gt;
            float s = 0.f;
#pragma unroll
            for (int k = 0; k < 8; k++) s += spart[k][rl];
            gate[gt] = s;
        }
        float gi = gate[0] + bih[j]         + bhh[j];
        float gf = gate[1] + bih[H + j]     + bhh[H + j];
        float gg = gate[2] + bih[2 * H + j] + bhh[2 * H + j];
        float go = gate[3] + bih[3 * H + j] + bhh[3 * H + j];
        float i_ = 1.0f / (1.0f + expf(-gi));
        float f_ = 1.0f / (1.0f + expf(-gf));
        float g_ = tanhf(gg);
        float o_ = 1.0f / (1.0f + expf(-go));
        float cn = f_ * g_c[layer][j] + i_ * g_;
        g_c[layer][j] = cn;
        g_h[par_out][layer][j] = o_ * tanhf(cn);
    }
}

// ---------------- fused head + sample ----------------
__global__ void __launch_bounds__(256)
head_sample_kernel(const float* __restrict__ hw, const float* __restrict__ hb,
                   const float* __restrict__ action_emb,
                   int t, float* __restrict__ out, int out_size) {
    const int r    = blockIdx.x & (NACT - 1);
    const int half = blockIdx.x >> 6;
    const int tid  = threadIdx.x;
    const int par_out = (t + 1) & 1;

    {
        const float4* row = reinterpret_cast<const float4*>(hw + (size_t)r * H);
        const float4* v4  = reinterpret_cast<const float4*>(g_h[par_out][1]);
        int k = half * 256 + tid;
        float4 a = row[k];
        float4 b = v4[k];
        float s = a.x * b.x + a.y * b.y + a.z * b.z + a.w * b.w;
#pragma unroll
        for (int o = 16; o; o >>= 1) s += __shfl_xor_sync(0xffffffffu, s, o);
        __shared__ float sm[8];
        if ((tid & 31) == 0) sm[tid >> 5] = s;
        __syncthreads();
        if (tid == 0) {
            g_part[half][r] = sm[0] + sm[1] + sm[2] + sm[3]
                            + sm[4] + sm[5] + sm[6] + sm[7];
        }
    }

    __shared__ int s_last;
    if (tid == 0) {
        __threadfence();
        int old = atomicAdd(&g_done, 1);
        s_last = (old == 2 * NACT - 1) ? 1 : 0;
        if (s_last) g_done = 0;
    }
    __syncthreads();
    if (!s_last) return;
    __threadfence();

    __shared__ float sl[NACT];
    if (tid < 32) {
        const int lane = tid;
        float l0 = g_part[0][lane]      + g_part[1][lane]      + hb[lane];
        float l1 = g_part[0][lane + 32] + g_part[1][lane + 32] + hb[lane + 32];
        sl[lane] = l0;
        sl[lane + 32] = l1;

        uint32_t kk0, kk1;
        threefry2x32(0u, 42u, 0u, (uint32_t)t, kk0, kk1);
        uint32_t a0, a1, b0, b1;
        threefry2x32(kk0, kk1, 0u, (uint32_t)lane,        a0, a1);
        threefry2x32(kk0, kk1, 0u, (uint32_t)(lane + 32), b0, b1);
        float u0 = jax_uniform(a0 ^ a1);
        float u1 = jax_uniform(b0 ^ b1);
        float gum0 = -logf(-logf(u0));
        float gum1 = -logf(-logf(u1));

        float v0 = l0 + gum0;
        float v1 = l1 + gum1;

        float bestv; int besti;
        if (v1 > v0) { bestv = v1; besti = lane + 32; }
        else         { bestv = v0; besti = lane; }
#pragma unroll
        for (int o = 16; o; o >>= 1) {
            float ov = __shfl_xor_sync(0xffffffffu, bestv, o);
            int   oi = __shfl_xor_sync(0xffffffffu, besti, o);
            if (ov > bestv || (ov == bestv && oi < besti)) { bestv = ov; besti = oi; }
        }
        float mx = fmaxf(l0, l1);
#pragma unroll
        for (int o = 16; o; o >>= 1) mx = fmaxf(mx, __shfl_xor_sync(0xffffffffu, mx, o));
        float se = expf(l0 - mx) + expf(l1 - mx);
#pragma unroll
        for (int o = 16; o; o >>= 1) se += __shfl_xor_sync(0xffffffffu, se, o);

        if (lane == 0) {
            float logp = (sl[besti] - mx) - logf(se);
            float news = g_logp_sum + logp;
            g_logp_sum = news;
            g_action   = besti;
            out[t] = (float)besti;
            if (t == STEPS - 1 && out_size > STEPS) out[STEPS] = news;
        }
    }
    __syncthreads();
    int a = g_action;
    const float* src = action_emb + (size_t)a * H;
    for (int k = tid; k < H; k += 256) g_x[k] = src[k];
}

// ---------------- launch ----------------
extern "C" void kernel_launch(void* const* d_in, const int* in_sizes, int n_in,
                              void* d_out, int out_size) {
    const float* start_token = (const float*)d_in[0];
    const float* action_emb  = (const float*)d_in[1];
    const float* w_ih        = (const float*)d_in[2];
    const float* w_hh        = (const float*)d_in[3];
    const float* b_ih        = (const float*)d_in[4];
    const float* b_hh        = (const float*)d_in[5];
    const float* head_w      = (const float*)d_in[6];
    const float* head_b      = (const float*)d_in[7];
    float* out = (float*)d_out;

    convert_kernel<<<4096, 256>>>(w_ih, w_hh);
    init_kernel<<<(H + 255) / 256, 256>>>(start_token);

    for (int t = 0; t < STEPS; t++) {
        for (int l = 0; l < NLAYERS; l++) {
            cell_kernel<<<512, 256>>>(b_ih + (size_t)l * 4 * H,
                                      b_hh + (size_t)l * 4 * H,
                                      l, t);
        }
        head_sample_kernel<<<2 * NACT, 256>>>(head_w + (size_t)t * NACT * H,
                                              head_b + (size_t)t * NACT,
                                              action_emb, t, out, out_size);
    }
}